// round 11
// baseline (speedup 1.0000x reference)
#include <cuda_runtime.h>
#include <cuda_bf16.h>
#include <math.h>
#include <stdint.h>

#define LEAKY 0.2f
typedef unsigned long long u64;

// ---------------------------------------------------------------------------
// Scratch (__device__ globals; no allocations allowed)
// ---------------------------------------------------------------------------
__device__ float g_asrc[64 * 1024];
__device__ float g_adst[64 * 1024];
__device__ __align__(16) __nv_bfloat16 g_Ah[8192 * 768];    // feat_in hi
__device__ __align__(16) __nv_bfloat16 g_Al[8192 * 768];    // feat_in lo
__device__ __align__(16) __nv_bfloat16 g_Wh[8 * 96 * 768];  // W^T [h][o][k] hi
__device__ __align__(16) __nv_bfloat16 g_Wl[8 * 96 * 768];
__device__ __align__(16) __nv_bfloat16 g_Hwh[768 * 768];    // Hw [o][k] hi
__device__ __align__(16) __nv_bfloat16 g_Hwl[768 * 768];
__device__ __align__(16) __nv_bfloat16 g_hTh[(size_t)64 * 96 * 1024]; // h^T [bh][o][n] hi
__device__ __align__(16) __nv_bfloat16 g_hTl[(size_t)64 * 96 * 1024]; // lo

// ---------------------------------------------------------------------------
// Warp-level bf16 MMA (sm_80+ PTX; lowers to HMMA on sm_103)
// ---------------------------------------------------------------------------
__device__ __forceinline__ void mma16816(float* c, const uint32_t* a, const uint32_t* b) {
    asm volatile(
        "mma.sync.aligned.m16n8k16.row.col.f32.bf16.bf16.f32 "
        "{%0,%1,%2,%3}, {%4,%5,%6,%7}, {%8,%9}, {%0,%1,%2,%3};"
        : "+f"(c[0]), "+f"(c[1]), "+f"(c[2]), "+f"(c[3])
        : "r"(a[0]), "r"(a[1]), "r"(a[2]), "r"(a[3]), "r"(b[0]), "r"(b[1]));
}
__device__ __forceinline__ uint32_t pack_bf2(float a, float b) {
    __nv_bfloat162 t = __floats2bfloat162_rn(a, b);
    return *(uint32_t*)&t;
}

// Double-buffered operand layout. Per buffer (stride 35840B):
//   AH 0 / AL 10240  : 128 rows x 80B
//   WH 20480 / WL 28160 : 96 rows x 80B
// 80B row stride is conflict-free for uint4 fills and 32-bit fragment loads.
#define BUF_STRIDE 35840
#define O_AH 0
#define O_AL 10240
#define O_WH 20480
#define O_WL 28160
// proj/gate: vec beyond both buffers; dtile [128][97] fp32 overlays buffers.
#define SM_VEC 71680
#define SM_TOT 72448
// attn: adst + row sums beyond buffers.
#define SM2_ADST 71680
#define SM2_SS   75776
#define SM2_TOT  76288

// ---------------------------------------------------------------------------
// Prep: fp32 -> (bf16 hi, bf16 lo) splits
// ---------------------------------------------------------------------------
__global__ __launch_bounds__(256) void k_prep_a(
    const float* __restrict__ A, const float* __restrict__ Hw)
{
    int i = blockIdx.x * 256 + threadIdx.x;
    if (i < 8192 * 768) {
        float x = A[i];
        __nv_bfloat16 hi = __float2bfloat16(x);
        g_Ah[i] = hi;
        g_Al[i] = __float2bfloat16(x - __bfloat162float(hi));
    }
    if (i < 768 * 768) {
        float x = Hw[i];
        __nv_bfloat16 hi = __float2bfloat16(x);
        g_Hwh[i] = hi;
        g_Hwl[i] = __float2bfloat16(x - __bfloat162float(hi));
    }
}
__global__ __launch_bounds__(256) void k_prep_w(const float* __restrict__ W)
{
    int i = blockIdx.x * 256 + threadIdx.x;
    if (i < 8 * 96 * 768) {
        int k = i % 768, t = i / 768;
        int o = t % 96, hh = t / 96;
        float x = W[((size_t)hh * 768 + k) * 96 + o];
        __nv_bfloat16 hi = __float2bfloat16(x);
        g_Wh[i] = hi;
        g_Wl[i] = __float2bfloat16(x - __bfloat162float(hi));
    }
}

// ---------------------------------------------------------------------------
// Shared MMA inner step: 2 k16 sub-steps on one buffer (A=PH-like, B=WH-like)
// ---------------------------------------------------------------------------
__device__ __forceinline__ void mma_chunk(
    const char* bp, float acc[2][6][4], int wm, int wn, int g, int tig)
{
#pragma unroll
    for (int ks = 0; ks < 2; ++ks) {
        const int kb = ks * 32;
        uint32_t ahi[2][4], alo[2][4];
#pragma unroll
        for (int ma = 0; ma < 2; ++ma) {
            int rb = wm * 32 + ma * 16;
            ahi[ma][0] = *(const uint32_t*)(bp + O_AH + (rb + g)     * 80 + kb + tig * 4);
            ahi[ma][1] = *(const uint32_t*)(bp + O_AH + (rb + g + 8) * 80 + kb + tig * 4);
            ahi[ma][2] = *(const uint32_t*)(bp + O_AH + (rb + g)     * 80 + kb + 16 + tig * 4);
            ahi[ma][3] = *(const uint32_t*)(bp + O_AH + (rb + g + 8) * 80 + kb + 16 + tig * 4);
            alo[ma][0] = *(const uint32_t*)(bp + O_AL + (rb + g)     * 80 + kb + tig * 4);
            alo[ma][1] = *(const uint32_t*)(bp + O_AL + (rb + g + 8) * 80 + kb + tig * 4);
            alo[ma][2] = *(const uint32_t*)(bp + O_AL + (rb + g)     * 80 + kb + 16 + tig * 4);
            alo[ma][3] = *(const uint32_t*)(bp + O_AL + (rb + g + 8) * 80 + kb + 16 + tig * 4);
        }
#pragma unroll
        for (int na = 0; na < 6; ++na) {
            int n = wn * 48 + na * 8 + g;
            uint32_t bhi[2], blo[2];
            bhi[0] = *(const uint32_t*)(bp + O_WH + n * 80 + kb + tig * 4);
            bhi[1] = *(const uint32_t*)(bp + O_WH + n * 80 + kb + 16 + tig * 4);
            blo[0] = *(const uint32_t*)(bp + O_WL + n * 80 + kb + tig * 4);
            blo[1] = *(const uint32_t*)(bp + O_WL + n * 80 + kb + 16 + tig * 4);
#pragma unroll
            for (int ma = 0; ma < 2; ++ma) {
                mma16816(acc[ma][na], ahi[ma], bhi);
                mma16816(acc[ma][na], ahi[ma], blo);
                mma16816(acc[ma][na], alo[ma], bhi);
            }
        }
    }
}

// ---------------------------------------------------------------------------
// Kernel 1 (HMMA, pipelined): h = feat_in @ W[h]; epilogue: a_src/a_dst + h^T.
// ---------------------------------------------------------------------------
__global__ __launch_bounds__(256) void k_proj_mma(
    const float* __restrict__ wsrc, const float* __restrict__ wdst)
{
    extern __shared__ __align__(16) char ds[];
    const int tid  = threadIdx.x;
    const int wid  = tid >> 5, lane = tid & 31;
    const int g    = lane >> 2, tig = lane & 3;
    const int wm   = wid & 3, wn = wid >> 2;
    const int row0 = blockIdx.x * 128, h = blockIdx.y;

    float* wsv = (float*)(ds + SM_VEC);
    if (tid < 96) {
        wsv[tid]      = wsrc[h * 96 + tid];
        wsv[96 + tid] = wdst[h * 96 + tid];
    }

    float acc[2][6][4];
#pragma unroll
    for (int ma = 0; ma < 2; ++ma)
#pragma unroll
        for (int na = 0; na < 6; ++na)
#pragma unroll
            for (int q = 0; q < 4; ++q) acc[ma][na][q] = 0.f;

    const uint4* __restrict__ Ah4 = (const uint4*)g_Ah;
    const uint4* __restrict__ Al4 = (const uint4*)g_Al;
    const uint4* __restrict__ Wh4 = (const uint4*)g_Wh;
    const uint4* __restrict__ Wl4 = (const uint4*)g_Wl;

    const int ar = tid >> 2, ac = tid & 3;     // A fill coords (iter adds 64 rows)
    const int wr = tid >> 2;                   // W fill coords
    uint4 rah[2], ral[2], rwh[2], rwl[2];

    // prologue: prefetch chunk 0
#pragma unroll
    for (int it = 0; it < 2; ++it) {
        int src = (row0 + ar + it * 64) * 96 + ac;
        rah[it] = Ah4[src];  ral[it] = Al4[src];
    }
    {
        int src = (h * 96 + wr) * 96 + ac;
        rwh[0] = Wh4[src];  rwl[0] = Wl4[src];
        if (tid < 128) {
            int s2 = (h * 96 + wr + 64) * 96 + ac;
            rwh[1] = Wh4[s2];  rwl[1] = Wl4[s2];
        }
    }

    for (int ch = 0; ch < 24; ++ch) {
        char* bp = ds + (ch & 1) * BUF_STRIDE;
#pragma unroll
        for (int it = 0; it < 2; ++it) {
            int r = ar + it * 64;
            *(uint4*)(bp + O_AH + r * 80 + ac * 16) = rah[it];
            *(uint4*)(bp + O_AL + r * 80 + ac * 16) = ral[it];
        }
        *(uint4*)(bp + O_WH + wr * 80 + ac * 16) = rwh[0];
        *(uint4*)(bp + O_WL + wr * 80 + ac * 16) = rwl[0];
        if (tid < 128) {
            *(uint4*)(bp + O_WH + (wr + 64) * 80 + ac * 16) = rwh[1];
            *(uint4*)(bp + O_WL + (wr + 64) * 80 + ac * 16) = rwl[1];
        }
        __syncthreads();
        if (ch < 23) {   // prefetch next chunk (LDG drains under the MMAs)
            int k4 = (ch + 1) * 4;
#pragma unroll
            for (int it = 0; it < 2; ++it) {
                int src = (row0 + ar + it * 64) * 96 + k4 + ac;
                rah[it] = Ah4[src];  ral[it] = Al4[src];
            }
            int src = (h * 96 + wr) * 96 + k4 + ac;
            rwh[0] = Wh4[src];  rwl[0] = Wl4[src];
            if (tid < 128) {
                int s2 = (h * 96 + wr + 64) * 96 + k4 + ac;
                rwh[1] = Wh4[s2];  rwl[1] = Wl4[s2];
            }
        }
        mma_chunk(bp, acc, wm, wn, g, tig);
    }
    __syncthreads();

    float* dtile = (float*)ds;   // [128][97] overlays buffers
#pragma unroll
    for (int ma = 0; ma < 2; ++ma)
#pragma unroll
        for (int na = 0; na < 6; ++na) {
            int rb = wm * 32 + ma * 16 + g;
            int cb = wn * 48 + na * 8 + 2 * tig;
            dtile[rb * 97 + cb]           = acc[ma][na][0];
            dtile[rb * 97 + cb + 1]       = acc[ma][na][1];
            dtile[(rb + 8) * 97 + cb]     = acc[ma][na][2];
            dtile[(rb + 8) * 97 + cb + 1] = acc[ma][na][3];
        }
    __syncthreads();

    const int batch = row0 >> 10, bh = batch * 8 + h;
    const int nbase = row0 & 1023;
    {   // a_src/a_dst: 2 threads per row
        int r = tid >> 1, half = tid & 1;
        float ps = 0.f, pd = 0.f;
#pragma unroll
        for (int cc = 0; cc < 48; ++cc) {
            int c = half * 48 + cc;
            float t = tanhf(dtile[r * 97 + c]);
            ps = fmaf(t, wsv[c], ps);
            pd = fmaf(t, wsv[96 + c], pd);
        }
        ps += __shfl_xor_sync(0xffffffffu, ps, 1);
        pd += __shfl_xor_sync(0xffffffffu, pd, 1);
        if (half == 0) {
            g_asrc[(size_t)bh * 1024 + nbase + r] = ps;
            g_adst[(size_t)bh * 1024 + nbase + r] = pd;
        }
    }
    // h^T bf16 split, coalesced along n (u32 = 2 bf16)
    for (int idx = tid; idx < 96 * 64; idx += 256) {
        int o = idx >> 6, nw = idx & 63;
        float v0 = dtile[(2 * nw) * 97 + o];
        float v1 = dtile[(2 * nw + 1) * 97 + o];
        __nv_bfloat16 b0 = __float2bfloat16(v0);
        __nv_bfloat16 b1 = __float2bfloat16(v1);
        uint32_t hi = pack_bf2(v0, v1);
        uint32_t lo = pack_bf2(v0 - __bfloat162float(b0), v1 - __bfloat162float(b1));
        size_t dst = ((size_t)bh * 96 + o) * 512 + (nbase >> 1) + nw;
        ((uint32_t*)g_hTh)[dst] = hi;
        ((uint32_t*)g_hTl)[dst] = lo;
    }
}

// ---------------------------------------------------------------------------
// Kernel 2 (HMMA, pipelined): single-pass masked softmax attention.
// exp(l) is safe unnormalized (tanh-bounded logits); exp(-999)=0 masks.
// p computed for chunk c+1 under the MMAs of chunk c.
// ---------------------------------------------------------------------------
__global__ __launch_bounds__(256) void k_attn_mma(
    const float* __restrict__ adj,   // [B,1024,1024]
    const float* __restrict__ bias,  // [96]
    float* __restrict__ out)         // [B,1024,768]
{
    extern __shared__ __align__(16) char ds[];
    const int tid = threadIdx.x;
    const int wid = tid >> 5, lane = tid & 31;
    const int g   = lane >> 2, tig = lane & 3;
    const int wm  = wid & 3, wn = wid >> 2;
    const int bh  = blockIdx.x, batch = bh >> 3, h = bh & 7;
    const int i0  = blockIdx.y * 128;

    float* adst_s = (float*)(ds + SM2_ADST);
    for (int j = tid; j < 1024; j += 256)
        adst_s[j] = g_adst[(size_t)bh * 1024 + j];

    const int pi = tid >> 1, phalf = tid & 1;
    const float asr = g_asrc[(size_t)bh * 1024 + i0 + pi];
    const float* adjrow = adj + ((size_t)batch * 1024 + i0 + pi) * 1024;
    float ssum = 0.f;

    float acc[2][6][4];
#pragma unroll
    for (int ma = 0; ma < 2; ++ma)
#pragma unroll
        for (int na = 0; na < 6; ++na)
#pragma unroll
            for (int q = 0; q < 4; ++q) acc[ma][na][q] = 0.f;

    const uint4* __restrict__ Hh4 = (const uint4*)g_hTh;
    const uint4* __restrict__ Hl4 = (const uint4*)g_hTl;
    const int hr = tid >> 2, hc = tid & 3;   // h^T fill coords
    uint4 rhh[2], rhl[2];
    uint32_t ppH[8], ppL[8];

    __syncthreads();   // adst_s ready

    // prologue: prefetch h^T chunk 0 + compute p chunk 0
    {
        int src = (bh * 96 + hr) * 128 + hc;
        rhh[0] = Hh4[src];  rhl[0] = Hl4[src];
        if (tid < 128) {
            int s2 = (bh * 96 + hr + 64) * 128 + hc;
            rhh[1] = Hh4[s2];  rhl[1] = Hl4[s2];
        }
#pragma unroll
        for (int q = 0; q < 4; ++q) {
            int j = phalf * 16 + q * 4;
            float4 av = *(const float4*)(adjrow + j);
            float ap[4] = {av.x, av.y, av.z, av.w};
            float pv[4];
#pragma unroll
            for (int t = 0; t < 4; ++t) {
                float l = asr + adst_s[j + t];
                l = l >= 0.f ? l : LEAKY * l;
                l = (ap[t] == 0.f) ? -999.f : l;
                float p = __expf(l);
                ssum += p;
                pv[t] = p;
            }
            __nv_bfloat16 b0 = __float2bfloat16(pv[0]);
            __nv_bfloat16 b1 = __float2bfloat16(pv[1]);
            __nv_bfloat16 b2 = __float2bfloat16(pv[2]);
            __nv_bfloat16 b3 = __float2bfloat16(pv[3]);
            ppH[2 * q]     = pack_bf2(pv[0], pv[1]);
            ppH[2 * q + 1] = pack_bf2(pv[2], pv[3]);
            ppL[2 * q]     = pack_bf2(pv[0] - __bfloat162float(b0), pv[1] - __bfloat162float(b1));
            ppL[2 * q + 1] = pack_bf2(pv[2] - __bfloat162float(b2), pv[3] - __bfloat162float(b3));
        }
    }

    for (int cc = 0; cc < 32; ++cc) {
        char* bp = ds + (cc & 1) * BUF_STRIDE;
        // store prefetched chunk cc
        *(uint4*)(bp + O_WH + hr * 80 + hc * 16) = rhh[0];
        *(uint4*)(bp + O_WL + hr * 80 + hc * 16) = rhl[0];
        if (tid < 128) {
            *(uint4*)(bp + O_WH + (hr + 64) * 80 + hc * 16) = rhh[1];
            *(uint4*)(bp + O_WL + (hr + 64) * 80 + hc * 16) = rhl[1];
        }
        {
            int off = pi * 80 + phalf * 32;
#pragma unroll
            for (int q = 0; q < 4; ++q) {
                *(uint32_t*)(bp + O_AH + off + q * 8)     = ppH[2 * q];
                *(uint32_t*)(bp + O_AH + off + q * 8 + 4) = ppH[2 * q + 1];
                *(uint32_t*)(bp + O_AL + off + q * 8)     = ppL[2 * q];
                *(uint32_t*)(bp + O_AL + off + q * 8 + 4) = ppL[2 * q + 1];
            }
        }
        __syncthreads();
        if (cc < 31) {   // prefetch + compute p for chunk cc+1 under the MMAs
            int j0 = (cc + 1) * 32;
            int src = (bh * 96 + hr) * 128 + (j0 >> 3) + hc;
            rhh[0] = Hh4[src];  rhl[0] = Hl4[src];
            if (tid < 128) {
                int s2 = (bh * 96 + hr + 64) * 128 + (j0 >> 3) + hc;
                rhh[1] = Hh4[s2];  rhl[1] = Hl4[s2];
            }
#pragma unroll
            for (int q = 0; q < 4; ++q) {
                int j = j0 + phalf * 16 + q * 4;
                float4 av = *(const float4*)(adjrow + j);
                float ap[4] = {av.x, av.y, av.z, av.w};
                float pv[4];
#pragma unroll
                for (int t = 0; t < 4; ++t) {
                    float l = asr + adst_s[j + t];
                    l = l >= 0.f ? l : LEAKY * l;
                    l = (ap[t] == 0.f) ? -999.f : l;
                    float p = __expf(l);
                    ssum += p;
                    pv[t] = p;
                }
                __nv_bfloat16 b0 = __float2bfloat16(pv[0]);
                __nv_bfloat16 b1 = __float2bfloat16(pv[1]);
                __nv_bfloat16 b2 = __float2bfloat16(pv[2]);
                __nv_bfloat16 b3 = __float2bfloat16(pv[3]);
                ppH[2 * q]     = pack_bf2(pv[0], pv[1]);
                ppH[2 * q + 1] = pack_bf2(pv[2], pv[3]);
                ppL[2 * q]     = pack_bf2(pv[0] - __bfloat162float(b0), pv[1] - __bfloat162float(b1));
                ppL[2 * q + 1] = pack_bf2(pv[2] - __bfloat162float(b2), pv[3] - __bfloat162float(b3));
            }
        }
        mma_chunk(bp, acc, wm, wn, g, tig);
    }

    // row sums
    ssum += __shfl_xor_sync(0xffffffffu, ssum, 1);
    float* ss = (float*)(ds + SM2_SS);
    if (phalf == 0) ss[pi] = ssum;
    __syncthreads();

    float* dtile = (float*)ds;
#pragma unroll
    for (int ma = 0; ma < 2; ++ma)
#pragma unroll
        for (int na = 0; na < 6; ++na) {
            int rb = wm * 32 + ma * 16 + g;
            int cb = wn * 48 + na * 8 + 2 * tig;
            dtile[rb * 97 + cb]           = acc[ma][na][0];
            dtile[rb * 97 + cb + 1]       = acc[ma][na][1];
            dtile[(rb + 8) * 97 + cb]     = acc[ma][na][2];
            dtile[(rb + 8) * 97 + cb + 1] = acc[ma][na][3];
        }
    __syncthreads();

    for (int i = tid; i < 128 * 96; i += 256) {
        int r = i / 96, c = i - r * 96;
        float v = dtile[r * 97 + c] * (1.f / ss[r]) + __ldg(&bias[c]);
        v = v > 0.f ? v : expm1f(v);
        out[((size_t)batch * 1024 + i0 + r) * 768 + h * 96 + c] = v;
    }
}

// ---------------------------------------------------------------------------
// Kernel 3 (HMMA, pipelined): gate GEMM + sigmoid + blend in-place.
// ---------------------------------------------------------------------------
__global__ __launch_bounds__(256) void k_gate_mma(
    const float* __restrict__ X, const float* __restrict__ Hb,
    float* __restrict__ out)
{
    extern __shared__ __align__(16) char ds[];
    const int tid  = threadIdx.x;
    const int wid  = tid >> 5, lane = tid & 31;
    const int g    = lane >> 2, tig = lane & 3;
    const int wm   = wid & 3, wn = wid >> 2;
    const int row0 = blockIdx.x * 128, c0 = blockIdx.y * 96;

    float* hbv = (float*)(ds + SM_VEC);
    if (tid < 96) hbv[tid] = Hb[c0 + tid];

    float acc[2][6][4];
#pragma unroll
    for (int ma = 0; ma < 2; ++ma)
#pragma unroll
        for (int na = 0; na < 6; ++na)
#pragma unroll
            for (int q = 0; q < 4; ++q) acc[ma][na][q] = 0.f;

    const uint4* __restrict__ Ah4 = (const uint4*)g_Ah;
    const uint4* __restrict__ Al4 = (const uint4*)g_Al;
    const uint4* __restrict__ Wh4 = (const uint4*)g_Hwh;
    const uint4* __restrict__ Wl4 = (const uint4*)g_Hwl;

    const int ar = tid >> 2, ac = tid & 3;
    const int wr = tid >> 2;
    uint4 rah[2], ral[2], rwh[2], rwl[2];

#pragma unroll
    for (int it = 0; it < 2; ++it) {
        int src = (row0 + ar + it * 64) * 96 + ac;
        rah[it] = Ah4[src];  ral[it] = Al4[src];
    }
    {
        int src = (c0 + wr) * 96 + ac;
        rwh[0] = Wh4[src];  rwl[0] = Wl4[src];
        if (tid < 128) {
            int s2 = (c0 + wr + 64) * 96 + ac;
            rwh[1] = Wh4[s2];  rwl[1] = Wl4[s2];
        }
    }

    for (int ch = 0; ch < 24; ++ch) {
        char* bp = ds + (ch & 1) * BUF_STRIDE;
#pragma unroll
        for (int it = 0; it < 2; ++it) {
            int r = ar + it * 64;
            *(uint4*)(bp + O_AH + r * 80 + ac * 16) = rah[it];
            *(uint4*)(bp + O_AL + r * 80 + ac * 16) = ral[it];
        }
        *(uint4*)(bp + O_WH + wr * 80 + ac * 16) = rwh[0];
        *(uint4*)(bp + O_WL + wr * 80 + ac * 16) = rwl[0];
        if (tid < 128) {
            *(uint4*)(bp + O_WH + (wr + 64) * 80 + ac * 16) = rwh[1];
            *(uint4*)(bp + O_WL + (wr + 64) * 80 + ac * 16) = rwl[1];
        }
        __syncthreads();
        if (ch < 23) {
            int k4 = (ch + 1) * 4;
#pragma unroll
            for (int it = 0; it < 2; ++it) {
                int src = (row0 + ar + it * 64) * 96 + k4 + ac;
                rah[it] = Ah4[src];  ral[it] = Al4[src];
            }
            int src = (c0 + wr) * 96 + k4 + ac;
            rwh[0] = Wh4[src];  rwl[0] = Wl4[src];
            if (tid < 128) {
                int s2 = (c0 + wr + 64) * 96 + k4 + ac;
                rwh[1] = Wh4[s2];  rwl[1] = Wl4[s2];
            }
        }
        mma_chunk(bp, acc, wm, wn, g, tig);
    }
    __syncthreads();

    float* dtile = (float*)ds;
#pragma unroll
    for (int ma = 0; ma < 2; ++ma)
#pragma unroll
        for (int na = 0; na < 6; ++na) {
            int rb = wm * 32 + ma * 16 + g;
            int cb = wn * 48 + na * 8 + 2 * tig;
            dtile[rb * 97 + cb]           = acc[ma][na][0];
            dtile[rb * 97 + cb + 1]       = acc[ma][na][1];
            dtile[(rb + 8) * 97 + cb]     = acc[ma][na][2];
            dtile[(rb + 8) * 97 + cb + 1] = acc[ma][na][3];
        }
    __syncthreads();

    for (int i = tid; i < 128 * 96; i += 256) {
        int r = i / 96, c = i - r * 96;
        int row = row0 + r, col = c0 + c;
        float v = dtile[r * 97 + c];
        float gg = 1.f / (1.f + __expf(-(v + hbv[c])));
        size_t idx = (size_t)row * 768 + col;
        float fo = out[idx], xi = X[idx];
        out[idx] = fmaf(gg, fo - xi, xi);
    }
}

// ---------------------------------------------------------------------------
// Inputs (metadata order): feat_in, adj, W, b, w_src, w_dst, Hw, Hb
// ---------------------------------------------------------------------------
extern "C" void kernel_launch(void* const* d_in, const int* in_sizes, int n_in,
                              void* d_out, int out_size)
{
    const float* feat_in = (const float*)d_in[0];
    const float* adj     = (const float*)d_in[1];
    const float* W       = (const float*)d_in[2];
    const float* bias    = (const float*)d_in[3];
    const float* wsrc    = (const float*)d_in[4];
    const float* wdst    = (const float*)d_in[5];
    const float* Hw      = (const float*)d_in[6];
    const float* Hb      = (const float*)d_in[7];
    float* out           = (float*)d_out;
    (void)in_sizes; (void)n_in; (void)out_size;

    static bool attr_done = false;
    if (!attr_done) {
        cudaFuncSetAttribute(k_proj_mma, cudaFuncAttributeMaxDynamicSharedMemorySize, SM_TOT);
        cudaFuncSetAttribute(k_attn_mma, cudaFuncAttributeMaxDynamicSharedMemorySize, SM2_TOT);
        cudaFuncSetAttribute(k_gate_mma, cudaFuncAttributeMaxDynamicSharedMemorySize, SM_TOT);
        attr_done = true;
    }

    k_prep_a<<<(8192 * 768 + 255) / 256, 256>>>(feat_in, Hw);
    k_prep_w<<<(8 * 96 * 768 + 255) / 256, 256>>>(W);
    k_proj_mma<<<dim3(64, 8), 256, SM_TOT>>>(wsrc, wdst);
    k_attn_mma<<<dim3(64, 8), 256, SM2_TOT>>>(adj, bias, out);
    k_gate_mma<<<dim3(64, 8), 256, SM_TOT>>>(feat_in, Hb, out);
}

// round 12
// speedup vs baseline: 1.2362x; 1.2362x over previous
#include <cuda_runtime.h>
#include <cuda_bf16.h>
#include <math.h>
#include <stdint.h>

#define LEAKY 0.2f

// ---------------------------------------------------------------------------
// Scratch (__device__ globals; no allocations allowed)
// ---------------------------------------------------------------------------
__device__ float g_asrc[64 * 1024];
__device__ float g_adst[64 * 1024];
__device__ __align__(16) __nv_bfloat16 g_Ah[8192 * 768];    // feat_in hi
__device__ __align__(16) __nv_bfloat16 g_Al[8192 * 768];    // feat_in lo
__device__ __align__(16) __nv_bfloat16 g_Wh[8 * 96 * 768];  // W^T [h][o][k] hi
__device__ __align__(16) __nv_bfloat16 g_Wl[8 * 96 * 768];
__device__ __align__(16) __nv_bfloat16 g_Hwh[768 * 768];    // Hw [o][k] hi
__device__ __align__(16) __nv_bfloat16 g_Hwl[768 * 768];
__device__ __align__(16) __nv_bfloat16 g_hTh[(size_t)64 * 96 * 1024]; // h^T [bh][o][n] hi
__device__ __align__(16) __nv_bfloat16 g_hTl[(size_t)64 * 96 * 1024]; // lo

// ---------------------------------------------------------------------------
// Helpers
// ---------------------------------------------------------------------------
__device__ __forceinline__ void mma16816(float* c, const uint32_t* a, const uint32_t* b) {
    asm volatile(
        "mma.sync.aligned.m16n8k16.row.col.f32.bf16.bf16.f32 "
        "{%0,%1,%2,%3}, {%4,%5,%6,%7}, {%8,%9}, {%0,%1,%2,%3};"
        : "+f"(c[0]), "+f"(c[1]), "+f"(c[2]), "+f"(c[3])
        : "r"(a[0]), "r"(a[1]), "r"(a[2]), "r"(a[3]), "r"(b[0]), "r"(b[1]));
}
__device__ __forceinline__ uint32_t pack_bf2(float a, float b) {
    __nv_bfloat162 t = __floats2bfloat162_rn(a, b);
    return *(uint32_t*)&t;
}
__device__ __forceinline__ uint32_t smem_u32(const void* p) {
    uint32_t a;
    asm("{ .reg .u64 t; cvta.to.shared.u64 t, %1; cvt.u32.u64 %0, t; }"
        : "=r"(a) : "l"(p));
    return a;
}
__device__ __forceinline__ void cp16(uint32_t dst, const void* src) {
    asm volatile("cp.async.cg.shared.global [%0], [%1], 16;" :: "r"(dst), "l"(src));
}
#define CP_COMMIT() asm volatile("cp.async.commit_group;")
#define CP_WAIT0()  asm volatile("cp.async.wait_group 0;" ::: "memory")

// Double-buffered operand layout. Per buffer (stride 35840B):
//   AH 0 / AL 10240 : 128 rows x 80B ; WH 20480 / WL 28160 : 96 rows x 80B
// 80B row stride is conflict-free for uint4 fills and 32-bit fragment loads.
#define BUF_STRIDE 35840
#define O_AH 0
#define O_AL 10240
#define O_WH 20480
#define O_WL 28160
#define SM_VEC 71680
#define SM_TOT 72448
#define SM2_ADST 71680
#define SM2_SS   75776
#define SM2_TOT  76288

// ---------------------------------------------------------------------------
// Prep: fp32 -> (bf16 hi, bf16 lo) splits
// ---------------------------------------------------------------------------
__global__ __launch_bounds__(256) void k_prep_a(
    const float* __restrict__ A, const float* __restrict__ Hw)
{
    int i = blockIdx.x * 256 + threadIdx.x;
    if (i < 8192 * 768) {
        float x = A[i];
        __nv_bfloat16 hi = __float2bfloat16(x);
        g_Ah[i] = hi;
        g_Al[i] = __float2bfloat16(x - __bfloat162float(hi));
    }
    if (i < 768 * 768) {
        float x = Hw[i];
        __nv_bfloat16 hi = __float2bfloat16(x);
        g_Hwh[i] = hi;
        g_Hwl[i] = __float2bfloat16(x - __bfloat162float(hi));
    }
}
__global__ __launch_bounds__(256) void k_prep_w(const float* __restrict__ W)
{
    int i = blockIdx.x * 256 + threadIdx.x;
    if (i < 8 * 96 * 768) {
        int k = i % 768, t = i / 768;
        int o = t % 96, hh = t / 96;
        float x = W[((size_t)hh * 768 + k) * 96 + o];
        __nv_bfloat16 hi = __float2bfloat16(x);
        g_Wh[i] = hi;
        g_Wl[i] = __float2bfloat16(x - __bfloat162float(hi));
    }
}

// ---------------------------------------------------------------------------
// MMA inner step: 2 k16 sub-steps on one buffer
// ---------------------------------------------------------------------------
__device__ __forceinline__ void mma_chunk(
    const char* bp, float acc[2][6][4], int wm, int wn, int g, int tig)
{
#pragma unroll
    for (int ks = 0; ks < 2; ++ks) {
        const int kb = ks * 32;
        uint32_t ahi[2][4], alo[2][4];
#pragma unroll
        for (int ma = 0; ma < 2; ++ma) {
            int rb = wm * 32 + ma * 16;
            ahi[ma][0] = *(const uint32_t*)(bp + O_AH + (rb + g)     * 80 + kb + tig * 4);
            ahi[ma][1] = *(const uint32_t*)(bp + O_AH + (rb + g + 8) * 80 + kb + tig * 4);
            ahi[ma][2] = *(const uint32_t*)(bp + O_AH + (rb + g)     * 80 + kb + 16 + tig * 4);
            ahi[ma][3] = *(const uint32_t*)(bp + O_AH + (rb + g + 8) * 80 + kb + 16 + tig * 4);
            alo[ma][0] = *(const uint32_t*)(bp + O_AL + (rb + g)     * 80 + kb + tig * 4);
            alo[ma][1] = *(const uint32_t*)(bp + O_AL + (rb + g + 8) * 80 + kb + tig * 4);
            alo[ma][2] = *(const uint32_t*)(bp + O_AL + (rb + g)     * 80 + kb + 16 + tig * 4);
            alo[ma][3] = *(const uint32_t*)(bp + O_AL + (rb + g + 8) * 80 + kb + 16 + tig * 4);
        }
#pragma unroll
        for (int na = 0; na < 6; ++na) {
            int n = wn * 48 + na * 8 + g;
            uint32_t bhi[2], blo[2];
            bhi[0] = *(const uint32_t*)(bp + O_WH + n * 80 + kb + tig * 4);
            bhi[1] = *(const uint32_t*)(bp + O_WH + n * 80 + kb + 16 + tig * 4);
            blo[0] = *(const uint32_t*)(bp + O_WL + n * 80 + kb + tig * 4);
            blo[1] = *(const uint32_t*)(bp + O_WL + n * 80 + kb + 16 + tig * 4);
#pragma unroll
            for (int ma = 0; ma < 2; ++ma) {
                mma16816(acc[ma][na], ahi[ma], bhi);
                mma16816(acc[ma][na], ahi[ma], blo);
                mma16816(acc[ma][na], alo[ma], bhi);
            }
        }
    }
}

// ---------------------------------------------------------------------------
// Kernel 1 (HMMA + cp.async pipeline): h = feat_in @ W[h].
// ---------------------------------------------------------------------------
__global__ void __launch_bounds__(256, 2) k_proj_mma(
    const float* __restrict__ wsrc, const float* __restrict__ wdst)
{
    extern __shared__ __align__(16) char ds[];
    const uint32_t sb = smem_u32(ds);
    const int tid  = threadIdx.x;
    const int wid  = tid >> 5, lane = tid & 31;
    const int g    = lane >> 2, tig = lane & 3;
    const int wm   = wid & 3, wn = wid >> 2;
    const int row0 = blockIdx.x * 128, h = blockIdx.y;
    const int ar   = tid >> 2, ac = tid & 3;

    float* wsv = (float*)(ds + SM_VEC);
    if (tid < 96) {
        wsv[tid]      = wsrc[h * 96 + tid];
        wsv[96 + tid] = wdst[h * 96 + tid];
    }

    float acc[2][6][4];
#pragma unroll
    for (int ma = 0; ma < 2; ++ma)
#pragma unroll
        for (int na = 0; na < 6; ++na)
#pragma unroll
            for (int q = 0; q < 4; ++q) acc[ma][na][q] = 0.f;

    const uint4* __restrict__ Ah4 = (const uint4*)g_Ah;
    const uint4* __restrict__ Al4 = (const uint4*)g_Al;
    const uint4* __restrict__ Wh4 = (const uint4*)g_Wh;
    const uint4* __restrict__ Wl4 = (const uint4*)g_Wl;

    // fill chunk 0 -> buf 0
    {
        const int k4 = 0;
#pragma unroll
        for (int it = 0; it < 2; ++it) {
            int r = ar + it * 64;
            cp16(sb + O_AH + r * 80 + ac * 16, &Ah4[(row0 + r) * 96 + k4 + ac]);
            cp16(sb + O_AL + r * 80 + ac * 16, &Al4[(row0 + r) * 96 + k4 + ac]);
        }
        cp16(sb + O_WH + ar * 80 + ac * 16, &Wh4[(h * 96 + ar) * 96 + k4 + ac]);
        cp16(sb + O_WL + ar * 80 + ac * 16, &Wl4[(h * 96 + ar) * 96 + k4 + ac]);
        if (tid < 128) {
            cp16(sb + O_WH + (ar + 64) * 80 + ac * 16, &Wh4[(h * 96 + ar + 64) * 96 + k4 + ac]);
            cp16(sb + O_WL + (ar + 64) * 80 + ac * 16, &Wl4[(h * 96 + ar + 64) * 96 + k4 + ac]);
        }
        CP_COMMIT();
    }

    for (int ch = 0; ch < 24; ++ch) {
        CP_WAIT0();
        __syncthreads();                 // buf[ch&1] ready; prev MMA reads done
        if (ch < 23) {                   // async-fill chunk ch+1 under the MMAs
            uint32_t bb = sb + ((ch + 1) & 1) * BUF_STRIDE;
            const int k4 = (ch + 1) * 4;
#pragma unroll
            for (int it = 0; it < 2; ++it) {
                int r = ar + it * 64;
                cp16(bb + O_AH + r * 80 + ac * 16, &Ah4[(row0 + r) * 96 + k4 + ac]);
                cp16(bb + O_AL + r * 80 + ac * 16, &Al4[(row0 + r) * 96 + k4 + ac]);
            }
            cp16(bb + O_WH + ar * 80 + ac * 16, &Wh4[(h * 96 + ar) * 96 + k4 + ac]);
            cp16(bb + O_WL + ar * 80 + ac * 16, &Wl4[(h * 96 + ar) * 96 + k4 + ac]);
            if (tid < 128) {
                cp16(bb + O_WH + (ar + 64) * 80 + ac * 16, &Wh4[(h * 96 + ar + 64) * 96 + k4 + ac]);
                cp16(bb + O_WL + (ar + 64) * 80 + ac * 16, &Wl4[(h * 96 + ar + 64) * 96 + k4 + ac]);
            }
            CP_COMMIT();
        }
        mma_chunk(ds + (ch & 1) * BUF_STRIDE, acc, wm, wn, g, tig);
    }
    __syncthreads();

    float* dtile = (float*)ds;   // [128][97] overlays buffers
#pragma unroll
    for (int ma = 0; ma < 2; ++ma)
#pragma unroll
        for (int na = 0; na < 6; ++na) {
            int rb = wm * 32 + ma * 16 + g;
            int cb = wn * 48 + na * 8 + 2 * tig;
            dtile[rb * 97 + cb]           = acc[ma][na][0];
            dtile[rb * 97 + cb + 1]       = acc[ma][na][1];
            dtile[(rb + 8) * 97 + cb]     = acc[ma][na][2];
            dtile[(rb + 8) * 97 + cb + 1] = acc[ma][na][3];
        }
    __syncthreads();

    const int batch = row0 >> 10, bh = batch * 8 + h;
    const int nbase = row0 & 1023;
    {   // a_src/a_dst: 2 threads per row
        int r = tid >> 1, half = tid & 1;
        float ps = 0.f, pd = 0.f;
#pragma unroll
        for (int cc = 0; cc < 48; ++cc) {
            int c = half * 48 + cc;
            float t = tanhf(dtile[r * 97 + c]);
            ps = fmaf(t, wsv[c], ps);
            pd = fmaf(t, wsv[96 + c], pd);
        }
        ps += __shfl_xor_sync(0xffffffffu, ps, 1);
        pd += __shfl_xor_sync(0xffffffffu, pd, 1);
        if (half == 0) {
            g_asrc[(size_t)bh * 1024 + nbase + r] = ps;
            g_adst[(size_t)bh * 1024 + nbase + r] = pd;
        }
    }
    // h^T bf16 split, coalesced along n (u32 = 2 bf16)
    for (int idx = tid; idx < 96 * 64; idx += 256) {
        int o = idx >> 6, nw = idx & 63;
        float v0 = dtile[(2 * nw) * 97 + o];
        float v1 = dtile[(2 * nw + 1) * 97 + o];
        __nv_bfloat16 b0 = __float2bfloat16(v0);
        __nv_bfloat16 b1 = __float2bfloat16(v1);
        uint32_t hi = pack_bf2(v0, v1);
        uint32_t lo = pack_bf2(v0 - __bfloat162float(b0), v1 - __bfloat162float(b1));
        size_t dst = ((size_t)bh * 96 + o) * 512 + (nbase >> 1) + nw;
        ((uint32_t*)g_hTh)[dst] = hi;
        ((uint32_t*)g_hTl)[dst] = lo;
    }
}

// ---------------------------------------------------------------------------
// p-tile compute + store: unnormalized exp (tanh-bounded logits; exp(-999)=0
// masks), bf16 hi/lo split, streamed straight to the target buffer.
// ---------------------------------------------------------------------------
__device__ __forceinline__ void compute_p(
    const float* __restrict__ adjrow, const float* adst_s, float asr,
    int j0, int pi, int phalf, float& ssum, uint32_t bb)
{
    const int off = pi * 80 + phalf * 32;
#pragma unroll
    for (int q = 0; q < 4; ++q) {
        int j = j0 + phalf * 16 + q * 4;
        float4 av = *(const float4*)(adjrow + j);
        float ap[4] = {av.x, av.y, av.z, av.w};
        float pv[4];
#pragma unroll
        for (int t = 0; t < 4; ++t) {
            float l = asr + adst_s[j + t];
            l = l >= 0.f ? l : LEAKY * l;
            l = (ap[t] == 0.f) ? -999.f : l;
            float p = __expf(l);
            ssum += p;
            pv[t] = p;
        }
        __nv_bfloat16 b0 = __float2bfloat16(pv[0]);
        __nv_bfloat16 b1 = __float2bfloat16(pv[1]);
        __nv_bfloat16 b2 = __float2bfloat16(pv[2]);
        __nv_bfloat16 b3 = __float2bfloat16(pv[3]);
        uint32_t h0 = pack_bf2(pv[0], pv[1]);
        uint32_t h1 = pack_bf2(pv[2], pv[3]);
        uint32_t l0 = pack_bf2(pv[0] - __bfloat162float(b0), pv[1] - __bfloat162float(b1));
        uint32_t l1 = pack_bf2(pv[2] - __bfloat162float(b2), pv[3] - __bfloat162float(b3));
        asm volatile("st.shared.v2.b32 [%0], {%1, %2};"
                     :: "r"(bb + O_AH + off + q * 8), "r"(h0), "r"(h1) : "memory");
        asm volatile("st.shared.v2.b32 [%0], {%1, %2};"
                     :: "r"(bb + O_AL + off + q * 8), "r"(l0), "r"(l1) : "memory");
    }
}

// ---------------------------------------------------------------------------
// Kernel 2 (HMMA + cp.async pipeline): single-pass masked softmax attention.
// ---------------------------------------------------------------------------
__global__ void __launch_bounds__(256, 2) k_attn_mma(
    const float* __restrict__ adj,   // [B,1024,1024]
    const float* __restrict__ bias,  // [96]
    float* __restrict__ out)         // [B,1024,768]
{
    extern __shared__ __align__(16) char ds[];
    const uint32_t sb = smem_u32(ds);
    const int tid = threadIdx.x;
    const int wid = tid >> 5, lane = tid & 31;
    const int g   = lane >> 2, tig = lane & 3;
    const int wm  = wid & 3, wn = wid >> 2;
    const int bh  = blockIdx.x, batch = bh >> 3, h = bh & 7;
    const int i0  = blockIdx.y * 128;
    const int hr  = tid >> 2, hc = tid & 3;

    float* adst_s = (float*)(ds + SM2_ADST);
    for (int j = tid; j < 1024; j += 256)
        adst_s[j] = g_adst[(size_t)bh * 1024 + j];

    const int pi = tid >> 1, phalf = tid & 1;
    const float asr = g_asrc[(size_t)bh * 1024 + i0 + pi];
    const float* adjrow = adj + ((size_t)batch * 1024 + i0 + pi) * 1024;
    float ssum = 0.f;

    float acc[2][6][4];
#pragma unroll
    for (int ma = 0; ma < 2; ++ma)
#pragma unroll
        for (int na = 0; na < 6; ++na)
#pragma unroll
            for (int q = 0; q < 4; ++q) acc[ma][na][q] = 0.f;

    const uint4* __restrict__ Hh4 = (const uint4*)g_hTh;
    const uint4* __restrict__ Hl4 = (const uint4*)g_hTl;

    // async-fill h^T chunk 0 -> buf 0
    {
        cp16(sb + O_WH + hr * 80 + hc * 16, &Hh4[(bh * 96 + hr) * 128 + hc]);
        cp16(sb + O_WL + hr * 80 + hc * 16, &Hl4[(bh * 96 + hr) * 128 + hc]);
        if (tid < 128) {
            cp16(sb + O_WH + (hr + 64) * 80 + hc * 16, &Hh4[(bh * 96 + hr + 64) * 128 + hc]);
            cp16(sb + O_WL + (hr + 64) * 80 + hc * 16, &Hl4[(bh * 96 + hr + 64) * 128 + hc]);
        }
        CP_COMMIT();
    }
    __syncthreads();                       // adst_s visible
    compute_p(adjrow, adst_s, asr, 0, pi, phalf, ssum, sb);   // p0 -> buf0

    for (int cc = 0; cc < 32; ++cc) {
        CP_WAIT0();
        __syncthreads();                   // buf[cc&1] (p + h) ready; prev MMA done
        if (cc < 31) {                     // chunk cc+1 under the MMAs
            uint32_t bb = sb + ((cc + 1) & 1) * BUF_STRIDE;
            const int j8 = (cc + 1) * 4;   // j0 in uint4 units
            cp16(bb + O_WH + hr * 80 + hc * 16, &Hh4[(bh * 96 + hr) * 128 + j8 + hc]);
            cp16(bb + O_WL + hr * 80 + hc * 16, &Hl4[(bh * 96 + hr) * 128 + j8 + hc]);
            if (tid < 128) {
                cp16(bb + O_WH + (hr + 64) * 80 + hc * 16, &Hh4[(bh * 96 + hr + 64) * 128 + j8 + hc]);
                cp16(bb + O_WL + (hr + 64) * 80 + hc * 16, &Hl4[(bh * 96 + hr + 64) * 128 + j8 + hc]);
            }
            CP_COMMIT();
            compute_p(adjrow, adst_s, asr, (cc + 1) * 32, pi, phalf, ssum, bb);
        }
        mma_chunk(ds + (cc & 1) * BUF_STRIDE, acc, wm, wn, g, tig);
    }

    // row sums
    ssum += __shfl_xor_sync(0xffffffffu, ssum, 1);
    float* ss = (float*)(ds + SM2_SS);
    if (phalf == 0) ss[pi] = ssum;
    __syncthreads();

    float* dtile = (float*)ds;
#pragma unroll
    for (int ma = 0; ma < 2; ++ma)
#pragma unroll
        for (int na = 0; na < 6; ++na) {
            int rb = wm * 32 + ma * 16 + g;
            int cb = wn * 48 + na * 8 + 2 * tig;
            dtile[rb * 97 + cb]           = acc[ma][na][0];
            dtile[rb * 97 + cb + 1]       = acc[ma][na][1];
            dtile[(rb + 8) * 97 + cb]     = acc[ma][na][2];
            dtile[(rb + 8) * 97 + cb + 1] = acc[ma][na][3];
        }
    __syncthreads();

    for (int i = tid; i < 128 * 96; i += 256) {
        int r = i / 96, c = i - r * 96;
        float v = dtile[r * 97 + c] * (1.f / ss[r]) + __ldg(&bias[c]);
        v = v > 0.f ? v : expm1f(v);
        out[((size_t)batch * 1024 + i0 + r) * 768 + h * 96 + c] = v;
    }
}

// ---------------------------------------------------------------------------
// Kernel 3 (HMMA + cp.async pipeline): gate GEMM + sigmoid + blend in-place.
// ---------------------------------------------------------------------------
__global__ void __launch_bounds__(256, 2) k_gate_mma(
    const float* __restrict__ X, const float* __restrict__ Hb,
    float* __restrict__ out)
{
    extern __shared__ __align__(16) char ds[];
    const uint32_t sb = smem_u32(ds);
    const int tid  = threadIdx.x;
    const int wid  = tid >> 5, lane = tid & 31;
    const int g    = lane >> 2, tig = lane & 3;
    const int wm   = wid & 3, wn = wid >> 2;
    const int row0 = blockIdx.x * 128, c0 = blockIdx.y * 96;
    const int ar   = tid >> 2, ac = tid & 3;

    float* hbv = (float*)(ds + SM_VEC);
    if (tid < 96) hbv[tid] = Hb[c0 + tid];

    float acc[2][6][4];
#pragma unroll
    for (int ma = 0; ma < 2; ++ma)
#pragma unroll
        for (int na = 0; na < 6; ++na)
#pragma unroll
            for (int q = 0; q < 4; ++q) acc[ma][na][q] = 0.f;

    const uint4* __restrict__ Ah4 = (const uint4*)g_Ah;
    const uint4* __restrict__ Al4 = (const uint4*)g_Al;
    const uint4* __restrict__ Wh4 = (const uint4*)g_Hwh;
    const uint4* __restrict__ Wl4 = (const uint4*)g_Hwl;

    {
        const int k4 = 0;
#pragma unroll
        for (int it = 0; it < 2; ++it) {
            int r = ar + it * 64;
            cp16(sb + O_AH + r * 80 + ac * 16, &Ah4[(row0 + r) * 96 + k4 + ac]);
            cp16(sb + O_AL + r * 80 + ac * 16, &Al4[(row0 + r) * 96 + k4 + ac]);
        }
        cp16(sb + O_WH + ar * 80 + ac * 16, &Wh4[(c0 + ar) * 96 + k4 + ac]);
        cp16(sb + O_WL + ar * 80 + ac * 16, &Wl4[(c0 + ar) * 96 + k4 + ac]);
        if (tid < 128) {
            cp16(sb + O_WH + (ar + 64) * 80 + ac * 16, &Wh4[(c0 + ar + 64) * 96 + k4 + ac]);
            cp16(sb + O_WL + (ar + 64) * 80 + ac * 16, &Wl4[(c0 + ar + 64) * 96 + k4 + ac]);
        }
        CP_COMMIT();
    }

    for (int ch = 0; ch < 24; ++ch) {
        CP_WAIT0();
        __syncthreads();
        if (ch < 23) {
            uint32_t bb = sb + ((ch + 1) & 1) * BUF_STRIDE;
            const int k4 = (ch + 1) * 4;
#pragma unroll
            for (int it = 0; it < 2; ++it) {
                int r = ar + it * 64;
                cp16(bb + O_AH + r * 80 + ac * 16, &Ah4[(row0 + r) * 96 + k4 + ac]);
                cp16(bb + O_AL + r * 80 + ac * 16, &Al4[(row0 + r) * 96 + k4 + ac]);
            }
            cp16(bb + O_WH + ar * 80 + ac * 16, &Wh4[(c0 + ar) * 96 + k4 + ac]);
            cp16(bb + O_WL + ar * 80 + ac * 16, &Wl4[(c0 + ar) * 96 + k4 + ac]);
            if (tid < 128) {
                cp16(bb + O_WH + (ar + 64) * 80 + ac * 16, &Wh4[(c0 + ar + 64) * 96 + k4 + ac]);
                cp16(bb + O_WL + (ar + 64) * 80 + ac * 16, &Wl4[(c0 + ar + 64) * 96 + k4 + ac]);
            }
            CP_COMMIT();
        }
        mma_chunk(ds + (ch & 1) * BUF_STRIDE, acc, wm, wn, g, tig);
    }
    __syncthreads();

    float* dtile = (float*)ds;
#pragma unroll
    for (int ma = 0; ma < 2; ++ma)
#pragma unroll
        for (int na = 0; na < 6; ++na) {
            int rb = wm * 32 + ma * 16 + g;
            int cb = wn * 48 + na * 8 + 2 * tig;
            dtile[rb * 97 + cb]           = acc[ma][na][0];
            dtile[rb * 97 + cb + 1]       = acc[ma][na][1];
            dtile[(rb + 8) * 97 + cb]     = acc[ma][na][2];
            dtile[(rb + 8) * 97 + cb + 1] = acc[ma][na][3];
        }
    __syncthreads();

    for (int i = tid; i < 128 * 96; i += 256) {
        int r = i / 96, c = i - r * 96;
        int row = row0 + r, col = c0 + c;
        float v = dtile[r * 97 + c];
        float gg = 1.f / (1.f + __expf(-(v + hbv[c])));
        size_t idx = (size_t)row * 768 + col;
        float fo = out[idx], xi = X[idx];
        out[idx] = fmaf(gg, fo - xi, xi);
    }
}

// ---------------------------------------------------------------------------
// Inputs (metadata order): feat_in, adj, W, b, w_src, w_dst, Hw, Hb
// ---------------------------------------------------------------------------
extern "C" void kernel_launch(void* const* d_in, const int* in_sizes, int n_in,
                              void* d_out, int out_size)
{
    const float* feat_in = (const float*)d_in[0];
    const float* adj     = (const float*)d_in[1];
    const float* W       = (const float*)d_in[2];
    const float* bias    = (const float*)d_in[3];
    const float* wsrc    = (const float*)d_in[4];
    const float* wdst    = (const float*)d_in[5];
    const float* Hw      = (const float*)d_in[6];
    const float* Hb      = (const float*)d_in[7];
    float* out           = (float*)d_out;
    (void)in_sizes; (void)n_in; (void)out_size;

    static bool attr_done = false;
    if (!attr_done) {
        cudaFuncSetAttribute(k_proj_mma, cudaFuncAttributeMaxDynamicSharedMemorySize, SM_TOT);
        cudaFuncSetAttribute(k_attn_mma, cudaFuncAttributeMaxDynamicSharedMemorySize, SM2_TOT);
        cudaFuncSetAttribute(k_gate_mma, cudaFuncAttributeMaxDynamicSharedMemorySize, SM_TOT);
        attr_done = true;
    }

    k_prep_a<<<(8192 * 768 + 255) / 256, 256>>>(feat_in, Hw);
    k_prep_w<<<(8 * 96 * 768 + 255) / 256, 256>>>(W);
    k_proj_mma<<<dim3(64, 8), 256, SM_TOT>>>(wsrc, wdst);
    k_attn_mma<<<dim3(64, 8), 256, SM2_TOT>>>(adj, bias, out);
    k_gate_mma<<<dim3(64, 8), 256, SM_TOT>>>(feat_in, Hb, out);
}

// round 13
// speedup vs baseline: 1.2565x; 1.0165x over previous
#include <cuda_runtime.h>
#include <cuda_bf16.h>
#include <math.h>
#include <stdint.h>

#define LEAKY 0.2f

// ---------------------------------------------------------------------------
// Scratch (__device__ globals; no allocations allowed)
// ---------------------------------------------------------------------------
__device__ float g_asrc[64 * 1024];
__device__ float g_adst[64 * 1024];
__device__ __align__(16) __nv_bfloat16 g_Ah[8192 * 768];    // feat_in hi
__device__ __align__(16) __nv_bfloat16 g_Al[8192 * 768];    // feat_in lo
__device__ __align__(16) __nv_bfloat16 g_Wh[8 * 96 * 768];  // W^T [h][o][k] hi
__device__ __align__(16) __nv_bfloat16 g_Wl[8 * 96 * 768];
__device__ __align__(16) __nv_bfloat16 g_Hwh[768 * 768];    // Hw [o][k] hi
__device__ __align__(16) __nv_bfloat16 g_Hwl[768 * 768];
__device__ __align__(16) __nv_bfloat16 g_hTh[(size_t)64 * 96 * 1024]; // h^T [bh][o][n] hi
__device__ __align__(16) __nv_bfloat16 g_hTl[(size_t)64 * 96 * 1024]; // lo

// ---------------------------------------------------------------------------
// Helpers
// ---------------------------------------------------------------------------
__device__ __forceinline__ void mma16816(float* c, const uint32_t* a, const uint32_t* b) {
    asm volatile(
        "mma.sync.aligned.m16n8k16.row.col.f32.bf16.bf16.f32 "
        "{%0,%1,%2,%3}, {%4,%5,%6,%7}, {%8,%9}, {%0,%1,%2,%3};"
        : "+f"(c[0]), "+f"(c[1]), "+f"(c[2]), "+f"(c[3])
        : "r"(a[0]), "r"(a[1]), "r"(a[2]), "r"(a[3]), "r"(b[0]), "r"(b[1]));
}
__device__ __forceinline__ uint32_t pack_bf2(float a, float b) {
    __nv_bfloat162 t = __floats2bfloat162_rn(a, b);
    return *(uint32_t*)&t;
}
__device__ __forceinline__ uint32_t smem_u32(const void* p) {
    uint32_t a;
    asm("{ .reg .u64 t; cvta.to.shared.u64 t, %1; cvt.u32.u64 %0, t; }"
        : "=r"(a) : "l"(p));
    return a;
}
__device__ __forceinline__ void cp16(uint32_t dst, const void* src) {
    asm volatile("cp.async.cg.shared.global [%0], [%1], 16;" :: "r"(dst), "l"(src));
}
#define CP_COMMIT() asm volatile("cp.async.commit_group;")
#define CP_WAIT0()  asm volatile("cp.async.wait_group 0;" ::: "memory")
#define CP_WAIT1()  asm volatile("cp.async.wait_group 1;" ::: "memory")

// Operand buffer layout (per buffer, stride 35840B):
//   AH 0 / AL 10240 : 128 rows x 80B ; WH 20480 / WL 28160 : 96 rows x 80B
#define BUF_STRIDE 35840
#define O_AH 0
#define O_AL 10240
#define O_WH 20480
#define O_WL 28160
// proj/gate: 3 buffers + vec
#define SM3_VEC 107520
#define SM3_TOT 108288
// attn: 2 operand buffers + 2 adj stage buffers (rows padded to 144B) + adst + ss
#define SM2_AB     71680
#define AB_STRIDE  18432
#define SM2_ADST   108544
#define SM2_SS     112640
#define SM2_TOT    113152

// ---------------------------------------------------------------------------
// Prep: fp32 -> (bf16 hi, bf16 lo) splits
// ---------------------------------------------------------------------------
__global__ __launch_bounds__(256) void k_prep_a(
    const float* __restrict__ A, const float* __restrict__ Hw)
{
    int i = blockIdx.x * 256 + threadIdx.x;
    if (i < 8192 * 768) {
        float x = A[i];
        __nv_bfloat16 hi = __float2bfloat16(x);
        g_Ah[i] = hi;
        g_Al[i] = __float2bfloat16(x - __bfloat162float(hi));
    }
    if (i < 768 * 768) {
        float x = Hw[i];
        __nv_bfloat16 hi = __float2bfloat16(x);
        g_Hwh[i] = hi;
        g_Hwl[i] = __float2bfloat16(x - __bfloat162float(hi));
    }
}
__global__ __launch_bounds__(256) void k_prep_w(const float* __restrict__ W)
{
    int i = blockIdx.x * 256 + threadIdx.x;
    if (i < 8 * 96 * 768) {
        int k = i % 768, t = i / 768;
        int o = t % 96, hh = t / 96;
        float x = W[((size_t)hh * 768 + k) * 96 + o];
        __nv_bfloat16 hi = __float2bfloat16(x);
        g_Wh[i] = hi;
        g_Wl[i] = __float2bfloat16(x - __bfloat162float(hi));
    }
}

// ---------------------------------------------------------------------------
// MMA inner step: 2 k16 sub-steps on one buffer
// ---------------------------------------------------------------------------
__device__ __forceinline__ void mma_chunk(
    const char* bp, float acc[2][6][4], int wm, int wn, int g, int tig)
{
#pragma unroll
    for (int ks = 0; ks < 2; ++ks) {
        const int kb = ks * 32;
        uint32_t ahi[2][4], alo[2][4];
#pragma unroll
        for (int ma = 0; ma < 2; ++ma) {
            int rb = wm * 32 + ma * 16;
            ahi[ma][0] = *(const uint32_t*)(bp + O_AH + (rb + g)     * 80 + kb + tig * 4);
            ahi[ma][1] = *(const uint32_t*)(bp + O_AH + (rb + g + 8) * 80 + kb + tig * 4);
            ahi[ma][2] = *(const uint32_t*)(bp + O_AH + (rb + g)     * 80 + kb + 16 + tig * 4);
            ahi[ma][3] = *(const uint32_t*)(bp + O_AH + (rb + g + 8) * 80 + kb + 16 + tig * 4);
            alo[ma][0] = *(const uint32_t*)(bp + O_AL + (rb + g)     * 80 + kb + tig * 4);
            alo[ma][1] = *(const uint32_t*)(bp + O_AL + (rb + g + 8) * 80 + kb + tig * 4);
            alo[ma][2] = *(const uint32_t*)(bp + O_AL + (rb + g)     * 80 + kb + 16 + tig * 4);
            alo[ma][3] = *(const uint32_t*)(bp + O_AL + (rb + g + 8) * 80 + kb + 16 + tig * 4);
        }
#pragma unroll
        for (int na = 0; na < 6; ++na) {
            int n = wn * 48 + na * 8 + g;
            uint32_t bhi[2], blo[2];
            bhi[0] = *(const uint32_t*)(bp + O_WH + n * 80 + kb + tig * 4);
            bhi[1] = *(const uint32_t*)(bp + O_WH + n * 80 + kb + 16 + tig * 4);
            blo[0] = *(const uint32_t*)(bp + O_WL + n * 80 + kb + tig * 4);
            blo[1] = *(const uint32_t*)(bp + O_WL + n * 80 + kb + 16 + tig * 4);
#pragma unroll
            for (int ma = 0; ma < 2; ++ma) {
                mma16816(acc[ma][na], ahi[ma], bhi);
                mma16816(acc[ma][na], ahi[ma], blo);
                mma16816(acc[ma][na], alo[ma], bhi);
            }
        }
    }
}

// ---------------------------------------------------------------------------
// Kernel 1 (HMMA, 3-deep cp.async pipeline): h = feat_in @ W[h].
// ---------------------------------------------------------------------------
__global__ void __launch_bounds__(256, 2) k_proj_mma(
    const float* __restrict__ wsrc, const float* __restrict__ wdst)
{
    extern __shared__ __align__(16) char ds[];
    const uint32_t sb = smem_u32(ds);
    const int tid  = threadIdx.x;
    const int wid  = tid >> 5, lane = tid & 31;
    const int g    = lane >> 2, tig = lane & 3;
    const int wm   = wid & 3, wn = wid >> 2;
    const int row0 = blockIdx.x * 128, h = blockIdx.y;
    const int ar   = tid >> 2, ac = tid & 3;

    float* wsv = (float*)(ds + SM3_VEC);
    if (tid < 96) {
        wsv[tid]      = wsrc[h * 96 + tid];
        wsv[96 + tid] = wdst[h * 96 + tid];
    }

    float acc[2][6][4];
#pragma unroll
    for (int ma = 0; ma < 2; ++ma)
#pragma unroll
        for (int na = 0; na < 6; ++na)
#pragma unroll
            for (int q = 0; q < 4; ++q) acc[ma][na][q] = 0.f;

    const uint4* __restrict__ Ah4 = (const uint4*)g_Ah;
    const uint4* __restrict__ Al4 = (const uint4*)g_Al;
    const uint4* __restrict__ Wh4 = (const uint4*)g_Wh;
    const uint4* __restrict__ Wl4 = (const uint4*)g_Wl;

    auto fill = [&](uint32_t bb, int k4) {
#pragma unroll
        for (int it = 0; it < 2; ++it) {
            int r = ar + it * 64;
            cp16(bb + O_AH + r * 80 + ac * 16, &Ah4[(row0 + r) * 96 + k4 + ac]);
            cp16(bb + O_AL + r * 80 + ac * 16, &Al4[(row0 + r) * 96 + k4 + ac]);
        }
        cp16(bb + O_WH + ar * 80 + ac * 16, &Wh4[(h * 96 + ar) * 96 + k4 + ac]);
        cp16(bb + O_WL + ar * 80 + ac * 16, &Wl4[(h * 96 + ar) * 96 + k4 + ac]);
        if (tid < 128) {
            cp16(bb + O_WH + (ar + 64) * 80 + ac * 16, &Wh4[(h * 96 + ar + 64) * 96 + k4 + ac]);
            cp16(bb + O_WL + (ar + 64) * 80 + ac * 16, &Wl4[(h * 96 + ar + 64) * 96 + k4 + ac]);
        }
        CP_COMMIT();
    };

    fill(sb, 0);
    fill(sb + BUF_STRIDE, 4);

    for (int ch = 0; ch < 24; ++ch) {
        if (ch < 22) CP_WAIT1(); else CP_WAIT0();
        __syncthreads();
        if (ch < 22) fill(sb + ((ch + 2) % 3) * BUF_STRIDE, (ch + 2) * 4);
        mma_chunk(ds + (ch % 3) * BUF_STRIDE, acc, wm, wn, g, tig);
    }
    __syncthreads();

    float* dtile = (float*)ds;   // [128][97] overlays buffers
#pragma unroll
    for (int ma = 0; ma < 2; ++ma)
#pragma unroll
        for (int na = 0; na < 6; ++na) {
            int rb = wm * 32 + ma * 16 + g;
            int cb = wn * 48 + na * 8 + 2 * tig;
            dtile[rb * 97 + cb]           = acc[ma][na][0];
            dtile[rb * 97 + cb + 1]       = acc[ma][na][1];
            dtile[(rb + 8) * 97 + cb]     = acc[ma][na][2];
            dtile[(rb + 8) * 97 + cb + 1] = acc[ma][na][3];
        }
    __syncthreads();

    const int batch = row0 >> 10, bh = batch * 8 + h;
    const int nbase = row0 & 1023;
    {   // a_src/a_dst: 2 threads per row
        int r = tid >> 1, half = tid & 1;
        float ps = 0.f, pd = 0.f;
#pragma unroll
        for (int cc = 0; cc < 48; ++cc) {
            int c = half * 48 + cc;
            float t = tanhf(dtile[r * 97 + c]);
            ps = fmaf(t, wsv[c], ps);
            pd = fmaf(t, wsv[96 + c], pd);
        }
        ps += __shfl_xor_sync(0xffffffffu, ps, 1);
        pd += __shfl_xor_sync(0xffffffffu, pd, 1);
        if (half == 0) {
            g_asrc[(size_t)bh * 1024 + nbase + r] = ps;
            g_adst[(size_t)bh * 1024 + nbase + r] = pd;
        }
    }
    // h^T bf16 split, coalesced along n
    for (int idx = tid; idx < 96 * 64; idx += 256) {
        int o = idx >> 6, nw = idx & 63;
        float v0 = dtile[(2 * nw) * 97 + o];
        float v1 = dtile[(2 * nw + 1) * 97 + o];
        __nv_bfloat16 b0 = __float2bfloat16(v0);
        __nv_bfloat16 b1 = __float2bfloat16(v1);
        uint32_t hi = pack_bf2(v0, v1);
        uint32_t lo = pack_bf2(v0 - __bfloat162float(b0), v1 - __bfloat162float(b1));
        size_t dst = ((size_t)bh * 96 + o) * 512 + (nbase >> 1) + nw;
        ((uint32_t*)g_hTh)[dst] = hi;
        ((uint32_t*)g_hTl)[dst] = lo;
    }
}

// ---------------------------------------------------------------------------
// p-tile compute from SMEM-staged adj (LDS instead of LDG on critical path).
// Unnormalized exp (tanh-bounded logits; exp(-999)=0 masks), bf16 hi/lo split.
// ---------------------------------------------------------------------------
__device__ __forceinline__ void compute_p(
    const char* ds, uint32_t abase_off, const float* adst_s, float asr,
    int j0, int pi, int phalf, float& ssum, uint32_t bb)
{
    const int off = pi * 80 + phalf * 32;
#pragma unroll
    for (int q = 0; q < 4; ++q) {
        int jj = phalf * 16 + q * 4;
        float4 av = *(const float4*)(ds + abase_off + pi * 144 + jj * 4);
        float ap[4] = {av.x, av.y, av.z, av.w};
        float pv[4];
#pragma unroll
        for (int t = 0; t < 4; ++t) {
            float l = asr + adst_s[j0 + jj + t];
            l = l >= 0.f ? l : LEAKY * l;
            l = (ap[t] == 0.f) ? -999.f : l;
            float p = __expf(l);
            ssum += p;
            pv[t] = p;
        }
        __nv_bfloat16 b0 = __float2bfloat16(pv[0]);
        __nv_bfloat16 b1 = __float2bfloat16(pv[1]);
        __nv_bfloat16 b2 = __float2bfloat16(pv[2]);
        __nv_bfloat16 b3 = __float2bfloat16(pv[3]);
        uint32_t h0 = pack_bf2(pv[0], pv[1]);
        uint32_t h1 = pack_bf2(pv[2], pv[3]);
        uint32_t l0 = pack_bf2(pv[0] - __bfloat162float(b0), pv[1] - __bfloat162float(b1));
        uint32_t l1 = pack_bf2(pv[2] - __bfloat162float(b2), pv[3] - __bfloat162float(b3));
        asm volatile("st.shared.v2.b32 [%0], {%1, %2};"
                     :: "r"(bb + O_AH + off + q * 8), "r"(h0), "r"(h1) : "memory");
        asm volatile("st.shared.v2.b32 [%0], {%1, %2};"
                     :: "r"(bb + O_AL + off + q * 8), "r"(l0), "r"(l1) : "memory");
    }
}

// ---------------------------------------------------------------------------
// Kernel 2 (HMMA + SMEM-staged adj pipeline): masked softmax attention.
// ---------------------------------------------------------------------------
__global__ void __launch_bounds__(256, 2) k_attn_mma(
    const float* __restrict__ adj,   // [B,1024,1024]
    const float* __restrict__ bias,  // [96]
    float* __restrict__ out)         // [B,1024,768]
{
    extern __shared__ __align__(16) char ds[];
    const uint32_t sb = smem_u32(ds);
    const int tid = threadIdx.x;
    const int wid = tid >> 5, lane = tid & 31;
    const int g   = lane >> 2, tig = lane & 3;
    const int wm  = wid & 3, wn = wid >> 2;
    const int bh  = blockIdx.x, batch = bh >> 3, h = bh & 7;
    const int i0  = blockIdx.y * 128;
    const int hr  = tid >> 2, hc = tid & 3;

    float* adst_s = (float*)(ds + SM2_ADST);
    for (int j = tid; j < 1024; j += 256)
        adst_s[j] = g_adst[(size_t)bh * 1024 + j];

    const int pi = tid >> 1, phalf = tid & 1;
    const float asr = g_asrc[(size_t)bh * 1024 + i0 + pi];
    float ssum = 0.f;

    float acc[2][6][4];
#pragma unroll
    for (int ma = 0; ma < 2; ++ma)
#pragma unroll
        for (int na = 0; na < 6; ++na)
#pragma unroll
            for (int q = 0; q < 4; ++q) acc[ma][na][q] = 0.f;

    const uint4* __restrict__ Hh4  = (const uint4*)g_hTh;
    const uint4* __restrict__ Hl4  = (const uint4*)g_hTl;
    const uint4* __restrict__ adj4 = (const uint4*)adj;

    auto fill_h = [&](uint32_t bb, int j8) {
        cp16(bb + O_WH + hr * 80 + hc * 16, &Hh4[(bh * 96 + hr) * 128 + j8 + hc]);
        cp16(bb + O_WL + hr * 80 + hc * 16, &Hl4[(bh * 96 + hr) * 128 + j8 + hc]);
        if (tid < 128) {
            cp16(bb + O_WH + (hr + 64) * 80 + hc * 16, &Hh4[(bh * 96 + hr + 64) * 128 + j8 + hc]);
            cp16(bb + O_WL + (hr + 64) * 80 + hc * 16, &Hl4[(bh * 96 + hr + 64) * 128 + j8 + hc]);
        }
    };
    auto fill_adj = [&](uint32_t ab, int chunk) {   // 128 rows x 32 j
#pragma unroll
        for (int it = 0; it < 4; ++it) {
            int idx = tid + it * 256;
            int r = idx >> 3, c = idx & 7;
            cp16(ab + r * 144 + c * 16,
                 &adj4[((size_t)(batch * 1024 + i0 + r)) * 256 + chunk * 8 + c]);
        }
    };

    // prologue: h[0], adj[0], adj[1] in one group
    fill_h(sb, 0);
    fill_adj(sb + SM2_AB, 0);
    fill_adj(sb + SM2_AB + AB_STRIDE, 1);
    CP_COMMIT();
    CP_WAIT0();
    __syncthreads();                         // adst_s + staged data visible
    compute_p(ds, SM2_AB, adst_s, asr, 0, pi, phalf, ssum, sb);  // p[0] -> buf0

    for (int cc = 0; cc < 32; ++cc) {
        CP_WAIT0();
        __syncthreads();     // publishes p[cc], h[cc], adj[cc+1]; prev MMA done
        if (cc < 31) {
            fill_h(sb + ((cc + 1) & 1) * BUF_STRIDE, (cc + 1) * 4);
            if (cc < 30)
                fill_adj(sb + SM2_AB + (cc & 1) * AB_STRIDE, cc + 2);
            CP_COMMIT();
            compute_p(ds, SM2_AB + ((cc + 1) & 1) * AB_STRIDE, adst_s, asr,
                      (cc + 1) * 32, pi, phalf, ssum,
                      sb + ((cc + 1) & 1) * BUF_STRIDE);
        }
        mma_chunk(ds + (cc & 1) * BUF_STRIDE, acc, wm, wn, g, tig);
    }

    // row sums
    ssum += __shfl_xor_sync(0xffffffffu, ssum, 1);
    float* ss = (float*)(ds + SM2_SS);
    if (phalf == 0) ss[pi] = ssum;
    __syncthreads();

    float* dtile = (float*)ds;
#pragma unroll
    for (int ma = 0; ma < 2; ++ma)
#pragma unroll
        for (int na = 0; na < 6; ++na) {
            int rb = wm * 32 + ma * 16 + g;
            int cb = wn * 48 + na * 8 + 2 * tig;
            dtile[rb * 97 + cb]           = acc[ma][na][0];
            dtile[rb * 97 + cb + 1]       = acc[ma][na][1];
            dtile[(rb + 8) * 97 + cb]     = acc[ma][na][2];
            dtile[(rb + 8) * 97 + cb + 1] = acc[ma][na][3];
        }
    __syncthreads();

    for (int i = tid; i < 128 * 96; i += 256) {
        int r = i / 96, c = i - r * 96;
        float v = dtile[r * 97 + c] * (1.f / ss[r]) + __ldg(&bias[c]);
        v = v > 0.f ? v : expm1f(v);
        out[((size_t)batch * 1024 + i0 + r) * 768 + h * 96 + c] = v;
    }
}

// ---------------------------------------------------------------------------
// Kernel 3 (HMMA, 3-deep cp.async pipeline): gate GEMM + sigmoid + blend.
// ---------------------------------------------------------------------------
__global__ void __launch_bounds__(256, 2) k_gate_mma(
    const float* __restrict__ X, const float* __restrict__ Hb,
    float* __restrict__ out)
{
    extern __shared__ __align__(16) char ds[];
    const uint32_t sb = smem_u32(ds);
    const int tid  = threadIdx.x;
    const int wid  = tid >> 5, lane = tid & 31;
    const int g    = lane >> 2, tig = lane & 3;
    const int wm   = wid & 3, wn = wid >> 2;
    const int row0 = blockIdx.x * 128, c0 = blockIdx.y * 96;
    const int ar   = tid >> 2, ac = tid & 3;

    float* hbv = (float*)(ds + SM3_VEC);
    if (tid < 96) hbv[tid] = Hb[c0 + tid];

    float acc[2][6][4];
#pragma unroll
    for (int ma = 0; ma < 2; ++ma)
#pragma unroll
        for (int na = 0; na < 6; ++na)
#pragma unroll
            for (int q = 0; q < 4; ++q) acc[ma][na][q] = 0.f;

    const uint4* __restrict__ Ah4 = (const uint4*)g_Ah;
    const uint4* __restrict__ Al4 = (const uint4*)g_Al;
    const uint4* __restrict__ Wh4 = (const uint4*)g_Hwh;
    const uint4* __restrict__ Wl4 = (const uint4*)g_Hwl;

    auto fill = [&](uint32_t bb, int k4) {
#pragma unroll
        for (int it = 0; it < 2; ++it) {
            int r = ar + it * 64;
            cp16(bb + O_AH + r * 80 + ac * 16, &Ah4[(row0 + r) * 96 + k4 + ac]);
            cp16(bb + O_AL + r * 80 + ac * 16, &Al4[(row0 + r) * 96 + k4 + ac]);
        }
        cp16(bb + O_WH + ar * 80 + ac * 16, &Wh4[(c0 + ar) * 96 + k4 + ac]);
        cp16(bb + O_WL + ar * 80 + ac * 16, &Wl4[(c0 + ar) * 96 + k4 + ac]);
        if (tid < 128) {
            cp16(bb + O_WH + (ar + 64) * 80 + ac * 16, &Wh4[(c0 + ar + 64) * 96 + k4 + ac]);
            cp16(bb + O_WL + (ar + 64) * 80 + ac * 16, &Wl4[(c0 + ar + 64) * 96 + k4 + ac]);
        }
        CP_COMMIT();
    };

    fill(sb, 0);
    fill(sb + BUF_STRIDE, 4);

    for (int ch = 0; ch < 24; ++ch) {
        if (ch < 22) CP_WAIT1(); else CP_WAIT0();
        __syncthreads();
        if (ch < 22) fill(sb + ((ch + 2) % 3) * BUF_STRIDE, (ch + 2) * 4);
        mma_chunk(ds + (ch % 3) * BUF_STRIDE, acc, wm, wn, g, tig);
    }
    __syncthreads();

    float* dtile = (float*)ds;
#pragma unroll
    for (int ma = 0; ma < 2; ++ma)
#pragma unroll
        for (int na = 0; na < 6; ++na) {
            int rb = wm * 32 + ma * 16 + g;
            int cb = wn * 48 + na * 8 + 2 * tig;
            dtile[rb * 97 + cb]           = acc[ma][na][0];
            dtile[rb * 97 + cb + 1]       = acc[ma][na][1];
            dtile[(rb + 8) * 97 + cb]     = acc[ma][na][2];
            dtile[(rb + 8) * 97 + cb + 1] = acc[ma][na][3];
        }
    __syncthreads();

    for (int i = tid; i < 128 * 96; i += 256) {
        int r = i / 96, c = i - r * 96;
        int row = row0 + r, col = c0 + c;
        float v = dtile[r * 97 + c];
        float gg = 1.f / (1.f + __expf(-(v + hbv[c])));
        size_t idx = (size_t)row * 768 + col;
        float fo = out[idx], xi = X[idx];
        out[idx] = fmaf(gg, fo - xi, xi);
    }
}

// ---------------------------------------------------------------------------
// Inputs (metadata order): feat_in, adj, W, b, w_src, w_dst, Hw, Hb
// ---------------------------------------------------------------------------
extern "C" void kernel_launch(void* const* d_in, const int* in_sizes, int n_in,
                              void* d_out, int out_size)
{
    const float* feat_in = (const float*)d_in[0];
    const float* adj     = (const float*)d_in[1];
    const float* W       = (const float*)d_in[2];
    const float* bias    = (const float*)d_in[3];
    const float* wsrc    = (const float*)d_in[4];
    const float* wdst    = (const float*)d_in[5];
    const float* Hw      = (const float*)d_in[6];
    const float* Hb      = (const float*)d_in[7];
    float* out           = (float*)d_out;
    (void)in_sizes; (void)n_in; (void)out_size;

    static bool attr_done = false;
    if (!attr_done) {
        cudaFuncSetAttribute(k_proj_mma, cudaFuncAttributeMaxDynamicSharedMemorySize, SM3_TOT);
        cudaFuncSetAttribute(k_attn_mma, cudaFuncAttributeMaxDynamicSharedMemorySize, SM2_TOT);
        cudaFuncSetAttribute(k_gate_mma, cudaFuncAttributeMaxDynamicSharedMemorySize, SM3_TOT);
        attr_done = true;
    }

    k_prep_a<<<(8192 * 768 + 255) / 256, 256>>>(feat_in, Hw);
    k_prep_w<<<(8 * 96 * 768 + 255) / 256, 256>>>(W);
    k_proj_mma<<<dim3(64, 8), 256, SM3_TOT>>>(wsrc, wdst);
    k_attn_mma<<<dim3(64, 8), 256, SM2_TOT>>>(adj, bias, out);
    k_gate_mma<<<dim3(64, 8), 256, SM3_TOT>>>(feat_in, Hb, out);
}